// round 7
// baseline (speedup 1.0000x reference)
#include <cuda_runtime.h>
#include <math.h>

// Problem constants
#define BB      128
#define CC      3
#define HH      224
#define PN      14          // patches per side
#define PS      16          // patch size
#define NP      196         // PN*PN
#define DD      768
#define NC      1000
#define TOPK    20
#define KDIM    588         // C*NP
#define NPART   16          // partials for patch_grad reduction (8 batches each)

// -------- scratch (device globals; no runtime allocation) --------
__device__ float g_patch_partial[NP * NPART];
__device__ float g_attack_pooled[KDIM];     // c*196 + px*14 + py
__device__ float g_addvec[KDIM];            // mask[p] * attack_pooled
__device__ float g_pooled_in[BB * KDIM];    // [b][c*196 + p]
__device__ float g_logits[BB * NC];
__device__ float g_ce[BB];

// ============================================================================
// Kernel 1 (fused, HBM-bound): pool inputs+attack_w 16x16 means AND reduce
// patch_grad over (batch, dim). Two independent 77MB streams in one grid.
//   Pool blocks:   129*3*14 = 5418  (bb==128 -> attack_w)
//   Grad blocks:   196*16   = 3136
// blockDim = 224
// ============================================================================
#define POOL_BLOCKS (129 * CC * PN)   // 5418
#define GRAD_BLOCKS (NP * NPART)      // 3136

__global__ void k1_pool_and_reduce(const float* __restrict__ inputs,
                                   const float* __restrict__ attack_w,
                                   const float* __restrict__ patch_grad) {
    int blk = blockIdx.x;
    int t   = threadIdx.x;   // 0..223

    if (blk < POOL_BLOCKS) {
        int bb  = blk / (CC * PN);
        int rem = blk % (CC * PN);
        int c   = rem / PN;
        int px  = rem % PN;
        const float* src = (bb < BB)
            ? inputs   + ((size_t)(bb * CC + c) * HH + px * PS) * HH
            : attack_w + ((size_t)c * HH + px * PS) * HH;
        // thread t sums column t over the 16 rows of this patch-row
        float acc = 0.f;
        #pragma unroll
        for (int r = 0; r < PS; ++r) acc += src[r * HH + t];
        // reduce within groups of 16 lanes (one group per output patch column)
        #pragma unroll
        for (int off = 8; off > 0; off >>= 1)
            acc += __shfl_down_sync(0xffffffffu, acc, off, 16);
        if ((t & 15) == 0) {
            int iy  = t >> 4;                       // 0..13
            float v = acc * (1.0f / 256.0f);        // 16x16 mean
            int idx = c * NP + px * PN + iy;
            if (bb < BB) g_pooled_in[bb * KDIM + idx] = v;
            else         g_attack_pooled[idx]          = v;
        }
    } else {
        int gid  = blk - POOL_BLOCKS;
        int p    = gid >> 4;            // patch index
        int part = gid & 15;
        int b0   = part * (BB / NPART); // 8 batches per part
        float acc = 0.f;
        for (int b = b0; b < b0 + (BB / NPART); ++b) {
            const float* row = patch_grad + ((size_t)b * NP + p) * DD;
            for (int d = t; d < DD; d += 224) acc += row[d];
        }
        // deterministic block reduce: warp shfl tree, then 7 partials serially
        #pragma unroll
        for (int off = 16; off > 0; off >>= 1)
            acc += __shfl_down_sync(0xffffffffu, acc, off);
        __shared__ float ws[7];
        if ((t & 31) == 0) ws[t >> 5] = acc;
        __syncthreads();
        if (t == 0) {
            float s = 0.f;
            #pragma unroll
            for (int w = 0; w < 7; ++w) s += ws[w];
            g_patch_partial[p * NPART + part] = s;
        }
    }
}

// ============================================================================
// Kernel 2 (tiny): combine partials -> sum_patch[196]; rank-based top-20 mask
// (ties: lower index wins, matching jax.lax.top_k); build addvec = mask*attack.
// 1 block, 640 threads.
// ============================================================================
__global__ void k2_topk_mask() {
    __shared__ float         sv[NP];
    __shared__ unsigned char smask[NP];
    int t = threadIdx.x;
    if (t < NP) {
        float v = 0.f;
        #pragma unroll
        for (int i = 0; i < NPART; ++i) v += g_patch_partial[t * NPART + i];
        sv[t] = v;
    }
    __syncthreads();
    if (t < NP) {
        float v = sv[t];
        int rank = 0;
        for (int j = 0; j < NP; ++j) {
            float u = sv[j];
            rank += (u > v) || (u == v && j < t);
        }
        smask[t] = (rank < TOPK) ? 1 : 0;
    }
    __syncthreads();
    if (t < KDIM)
        g_addvec[t] = smask[t % NP] ? g_attack_pooled[t] : 0.0f;
}

// ============================================================================
// Kernel 3: SGEMM logits[128,1000] = (pooled_in + addvec)[128,588] @ w_cls.
// Mask folded into A-tile load. BM=16, BN=64, KT=84, 128 threads,
// grid (16, 8) = 128 blocks (~1 block/SM). Thread tile 2m x 4n.
// ============================================================================
#define BM 16
#define BN 64
#define KT 84

__global__ void k3_gemm(const float* __restrict__ w_cls) {
    __shared__ float sA[KT][BM];
    __shared__ float sW[KT][BN];
    int t  = threadIdx.x;
    int n0 = blockIdx.x * BN;
    int m0 = blockIdx.y * BM;
    int tn = t & 15;          // n-group (4 cols)
    int tm = t >> 4;          // m-group (2 rows)
    float acc[2][4] = {{0.f, 0.f, 0.f, 0.f}, {0.f, 0.f, 0.f, 0.f}};

    for (int kt = 0; kt < KDIM / KT; ++kt) {
        int k0 = kt * KT;
        for (int i = t; i < BM * KT; i += 128) {
            int m = i / KT;
            int k = i - m * KT;
            sA[k][m] = g_pooled_in[(m0 + m) * KDIM + k0 + k] + g_addvec[k0 + k];
        }
        for (int i = t; i < KT * BN; i += 128) {
            int kk = i >> 6;
            int n  = i & 63;
            int gn = n0 + n;
            sW[kk][n] = (gn < NC) ? w_cls[(size_t)(k0 + kk) * NC + gn] : 0.0f;
        }
        __syncthreads();
        #pragma unroll 4
        for (int k = 0; k < KT; ++k) {
            float2 a = *(const float2*)&sA[k][tm * 2];
            float4 w = *(const float4*)&sW[k][tn * 4];
            acc[0][0] += a.x * w.x; acc[0][1] += a.x * w.y;
            acc[0][2] += a.x * w.z; acc[0][3] += a.x * w.w;
            acc[1][0] += a.y * w.x; acc[1][1] += a.y * w.y;
            acc[1][2] += a.y * w.z; acc[1][3] += a.y * w.w;
        }
        __syncthreads();
    }
    #pragma unroll
    for (int r = 0; r < 2; ++r) {
        int m = m0 + tm * 2 + r;
        #pragma unroll
        for (int j = 0; j < 4; ++j) {
            int n = n0 + tn * 4 + j;
            if (n < NC) g_logits[m * NC + n] = acc[r][j];
        }
    }
}

// ============================================================================
// Kernel 4: per-row softmax -> probs (written to pdst), then log_softmax of
// the PROBS (reference quirk) -> ce[b] = lse(probs) - probs[target].
// grid = 128 blocks, 256 threads, 4 cols/thread. Deterministic tree reduces.
// ============================================================================
__global__ void k4_softmax_ce(const int* __restrict__ targets,
                              float* __restrict__ pdst) {
    int b = blockIdx.x;
    int t = threadIdx.x;
    const float* lrow = g_logits + (size_t)b * NC;
    __shared__ float red[256];
    __shared__ float ptgt;

    float l[4];
    float m = -INFINITY;
    #pragma unroll
    for (int i = 0; i < 4; ++i) {
        int j = t + i * 256;
        l[i] = (j < NC) ? lrow[j] : -INFINITY;
        m = fmaxf(m, l[i]);
    }
    red[t] = m; __syncthreads();
    for (int s = 128; s > 0; s >>= 1) { if (t < s) red[t] = fmaxf(red[t], red[t + s]); __syncthreads(); }
    float rowmax = red[0]; __syncthreads();

    float e[4]; float ssum = 0.f;
    #pragma unroll
    for (int i = 0; i < 4; ++i) {
        int j = t + i * 256;
        e[i] = (j < NC) ? __expf(l[i] - rowmax) : 0.f;
        ssum += e[i];
    }
    red[t] = ssum; __syncthreads();
    for (int s = 128; s > 0; s >>= 1) { if (t < s) red[t] += red[t + s]; __syncthreads(); }
    float inv = 1.0f / red[0]; __syncthreads();

    int tgt = targets[b];
    float p[4];
    #pragma unroll
    for (int i = 0; i < 4; ++i) {
        int j = t + i * 256;
        if (j < NC) {
            p[i] = e[i] * inv;
            pdst[(size_t)b * NC + j] = p[i];
            if (j == tgt) ptgt = p[i];
        } else p[i] = -INFINITY;   // sentinel for max, skipped in sum below
    }
    __syncthreads();

    // log-sum-exp over the probabilities
    float m2 = -INFINITY;
    #pragma unroll
    for (int i = 0; i < 4; ++i) m2 = fmaxf(m2, p[i]);
    red[t] = m2; __syncthreads();
    for (int s = 128; s > 0; s >>= 1) { if (t < s) red[t] = fmaxf(red[t], red[t + s]); __syncthreads(); }
    float pmax = red[0]; __syncthreads();

    float s2 = 0.f;
    #pragma unroll
    for (int i = 0; i < 4; ++i) {
        int j = t + i * 256;
        if (j < NC) s2 += __expf(p[i] - pmax);
    }
    red[t] = s2; __syncthreads();
    for (int s = 128; s > 0; s >>= 1) { if (t < s) red[t] += red[t + s]; __syncthreads(); }
    if (t == 0) {
        float lse = pmax + logf(red[0]);
        g_ce[b] = lse - ptgt;
    }
}

// ============================================================================
// Kernel 5: loss = -mean(ce). 1 warp, deterministic fixed-order reduce.
// ============================================================================
__global__ void k5_loss(float* __restrict__ out, int loss_idx) {
    int t = threadIdx.x;   // 32 threads
    float s = 0.f;
    #pragma unroll
    for (int i = 0; i < 4; ++i) s += g_ce[t * 4 + i];
    #pragma unroll
    for (int off = 16; off > 0; off >>= 1)
        s += __shfl_down_sync(0xffffffffu, s, off);
    if (t == 0 && loss_idx >= 0)
        out[loss_idx] = -(s * (1.0f / BB));
}

// ============================================================================
extern "C" void kernel_launch(void* const* d_in, const int* in_sizes, int n_in,
                              void* d_out, int out_size) {
    const float* inputs     = (const float*)d_in[0];   // [128,3,224,224]
    const float* patch_grad = (const float*)d_in[1];   // [128,196,768]
    const float* attack_w   = (const float*)d_in[2];   // [3,224,224]
    const float* w_cls      = (const float*)d_in[3];   // [588,1000]
    const int*   targets    = (const int*)d_in[4];     // [128]
    float* out = (float*)d_out;

    (void)in_sizes; (void)n_in;

    // Where do the probs / loss go?
    float* pdst = out;
    float* g_logits_dev = nullptr;
    if (out_size < BB * NC) {
        // out too small for probs: dump probs back over logits scratch
        cudaGetSymbolAddress((void**)&g_logits_dev, g_logits);
        pdst = g_logits_dev;
    }
    int loss_idx = -1;
    if (out_size >= BB * NC + 1)      loss_idx = BB * NC;
    else if (out_size == 1)           { loss_idx = 0; }

    k1_pool_and_reduce<<<POOL_BLOCKS + GRAD_BLOCKS, 224>>>(inputs, attack_w, patch_grad);
    k2_topk_mask<<<1, 640>>>();
    {
        dim3 grid(NC / BN + ((NC % BN) ? 1 : 0), BB / BM);   // (16, 8)
        k3_gemm<<<grid, 128>>>(w_cls);
    }
    k4_softmax_ce<<<BB, 256>>>(targets, pdst);
    k5_loss<<<1, 32>>>(out, loss_idx);
}

// round 9
// speedup vs baseline: 2.3450x; 2.3450x over previous
#include <cuda_runtime.h>
#include <math.h>

// Problem constants
#define BB      128
#define CC      3
#define HH      224
#define PN      14          // patches per side
#define PS      16          // patch size
#define NP      196         // PN*PN
#define DD      768
#define NC      1000
#define TOPK    20
#define KDIM    588         // C*NP
#define NPART   16          // partials for patch_grad reduction (8 batches each)
#define SPLITK  4
#define KSEG    147         // KDIM / SPLITK

// -------- scratch (device globals; no runtime allocation) --------
__device__ float g_patch_partial[NP * NPART];
__device__ float g_attack_pooled[KDIM];          // c*196 + px*14 + py
__device__ float g_addvec[KDIM];                 // mask[p] * attack_pooled
__device__ float g_pooled_in[BB * KDIM];         // [b][c*196 + p]
__device__ float g_logits_part[SPLITK][BB * NC]; // split-K partials
__device__ float g_logits[BB * NC];              // fallback probs dst
__device__ float g_ce[BB];

// ============================================================================
// Kernel 1 (fused, HBM-bound): pool inputs+attack_w 16x16 means AND reduce
// patch_grad over (batch, dim). Two independent 77MB streams in one grid.
//   Pool blocks: 129*3*14 = 5418  (bb==128 -> attack_w)
//   Grad blocks: 196*16   = 3136  (float4, fully unrolled: MLP = 8x16B/thread)
// blockDim = 224
// ============================================================================
#define POOL_BLOCKS (129 * CC * PN)   // 5418
#define GRAD_BLOCKS (NP * NPART)      // 3136

__global__ void k1_pool_and_reduce(const float* __restrict__ inputs,
                                   const float* __restrict__ attack_w,
                                   const float* __restrict__ patch_grad) {
    int blk = blockIdx.x;
    int t   = threadIdx.x;   // 0..223

    if (blk < POOL_BLOCKS) {
        int bb  = blk / (CC * PN);
        int rem = blk % (CC * PN);
        int c   = rem / PN;
        int px  = rem % PN;
        const float* src = (bb < BB)
            ? inputs   + ((size_t)(bb * CC + c) * HH + px * PS) * HH
            : attack_w + ((size_t)c * HH + px * PS) * HH;
        // thread t sums column t over the 16 rows of this patch-row (MLP=16)
        float acc = 0.f;
        #pragma unroll
        for (int r = 0; r < PS; ++r) acc += src[r * HH + t];
        // reduce within groups of 16 lanes (one group per output patch column)
        #pragma unroll
        for (int off = 8; off > 0; off >>= 1)
            acc += __shfl_down_sync(0xffffffffu, acc, off, 16);
        if ((t & 15) == 0) {
            int iy  = t >> 4;                       // 0..13
            float v = acc * (1.0f / 256.0f);        // 16x16 mean
            int idx = c * NP + px * PN + iy;
            if (bb < BB) g_pooled_in[bb * KDIM + idx] = v;
            else         g_attack_pooled[idx]          = v;
        }
    } else {
        int gid  = blk - POOL_BLOCKS;
        int p    = gid >> 4;            // patch index
        int part = gid & 15;
        int b0   = part * (BB / NPART); // 8 batches per part
        float acc = 0.f;
        if (t < DD / 4) {               // 192 threads carry float4 lanes
            #pragma unroll
            for (int bi = 0; bi < BB / NPART; ++bi) {
                const float4 v = reinterpret_cast<const float4*>(
                    patch_grad + ((size_t)(b0 + bi) * NP + p) * DD)[t];
                acc += (v.x + v.y) + (v.z + v.w);
            }
        }
        // deterministic block reduce: warp shfl tree, then 7 partials serially
        #pragma unroll
        for (int off = 16; off > 0; off >>= 1)
            acc += __shfl_down_sync(0xffffffffu, acc, off);
        __shared__ float ws[7];
        if ((t & 31) == 0) ws[t >> 5] = acc;
        __syncthreads();
        if (t == 0) {
            float s = 0.f;
            #pragma unroll
            for (int w = 0; w < 7; ++w) s += ws[w];
            g_patch_partial[p * NPART + part] = s;
        }
    }
}

// ============================================================================
// Kernel 2 (tiny): combine partials -> sum_patch[196]; rank-based top-20 mask
// (ties: lower index wins, matching jax.lax.top_k); build addvec = mask*attack.
// 1 block, 640 threads.
// ============================================================================
__global__ void k2_topk_mask() {
    __shared__ float         sv[NP];
    __shared__ unsigned char smask[NP];
    int t = threadIdx.x;
    if (t < NP) {
        float v = 0.f;
        #pragma unroll
        for (int i = 0; i < NPART; ++i) v += g_patch_partial[t * NPART + i];
        sv[t] = v;
    }
    __syncthreads();
    if (t < NP) {
        float v = sv[t];
        int rank = 0;
        for (int j = 0; j < NP; ++j) {
            float u = sv[j];
            rank += (u > v) || (u == v && j < t);
        }
        smask[t] = (rank < TOPK) ? 1 : 0;
    }
    __syncthreads();
    if (t < KDIM)
        g_addvec[t] = smask[t % NP] ? g_attack_pooled[t] : 0.0f;
}

// ============================================================================
// Kernel 3: split-K SGEMM partials:
//   logits[128,1000] = (pooled_in + addvec)[128,588] @ w_cls[588,1000]
// grid (16, 8, 4) = 512 blocks (~3.5/SM -> 14 warps/SM latency hiding),
// 128 threads, BM=16 x BN=64, KSEG=147 per z-slice (3 tiles of KT=49),
// thread tile 2m x 4n. Partials combined in fixed order in k4.
// ============================================================================
#define BM 16
#define BN 64
#define KT 49

__global__ void k3_gemm(const float* __restrict__ w_cls) {
    __shared__ float sA[KT][BM];
    __shared__ float sW[KT][BN];
    int t  = threadIdx.x;
    int n0 = blockIdx.x * BN;
    int m0 = blockIdx.y * BM;
    int kb = blockIdx.z * KSEG;
    int tn = t & 15;          // n-group (4 cols)
    int tm = t >> 4;          // m-group (2 rows)
    float acc[2][4] = {{0.f, 0.f, 0.f, 0.f}, {0.f, 0.f, 0.f, 0.f}};

    #pragma unroll
    for (int kt = 0; kt < KSEG / KT; ++kt) {
        int k0 = kb + kt * KT;
        #pragma unroll
        for (int i = t; i < BM * KT; i += 128) {
            int m = i / KT;
            int k = i - m * KT;
            sA[k][m] = g_pooled_in[(m0 + m) * KDIM + k0 + k] + g_addvec[k0 + k];
        }
        #pragma unroll
        for (int i = t; i < KT * BN; i += 128) {
            int kk = i >> 6;
            int n  = i & 63;
            int gn = n0 + n;
            sW[kk][n] = (gn < NC) ? w_cls[(size_t)(k0 + kk) * NC + gn] : 0.0f;
        }
        __syncthreads();
        #pragma unroll 7
        for (int k = 0; k < KT; ++k) {
            float2 a = *(const float2*)&sA[k][tm * 2];
            float4 w = *(const float4*)&sW[k][tn * 4];
            acc[0][0] += a.x * w.x; acc[0][1] += a.x * w.y;
            acc[0][2] += a.x * w.z; acc[0][3] += a.x * w.w;
            acc[1][0] += a.y * w.x; acc[1][1] += a.y * w.y;
            acc[1][2] += a.y * w.z; acc[1][3] += a.y * w.w;
        }
        __syncthreads();
    }
    float* dst = g_logits_part[blockIdx.z];
    #pragma unroll
    for (int r = 0; r < 2; ++r) {
        int m = m0 + tm * 2 + r;
        #pragma unroll
        for (int j = 0; j < 4; ++j) {
            int n = n0 + tn * 4 + j;
            if (n < NC) dst[m * NC + n] = acc[r][j];
        }
    }
}

// ============================================================================
// Kernel 4: combine split-K partials (fixed order), per-row softmax -> probs
// (written to pdst), then log_softmax of the PROBS (reference quirk):
//   ce[b] = log(sum_j exp(p_j)) - p_target     (p in (0,1] -> no shift needed)
// grid = 128 blocks, 256 threads, 4 cols/thread. Warp-shfl reductions.
// ============================================================================
__device__ __forceinline__ float warpMax(float v) {
    #pragma unroll
    for (int o = 16; o > 0; o >>= 1) v = fmaxf(v, __shfl_xor_sync(0xffffffffu, v, o));
    return v;
}
__device__ __forceinline__ float warpSum(float v) {
    #pragma unroll
    for (int o = 16; o > 0; o >>= 1) v += __shfl_xor_sync(0xffffffffu, v, o);
    return v;
}

__global__ void k4_softmax_ce(const int* __restrict__ targets,
                              float* __restrict__ pdst) {
    int b = blockIdx.x;
    int t = threadIdx.x;
    int w = t >> 5;
    __shared__ float red[8];
    __shared__ float ptgt;

    float l[4];
    float m = -INFINITY;
    #pragma unroll
    for (int i = 0; i < 4; ++i) {
        int j = t + i * 256;
        if (j < NC) {
            size_t o = (size_t)b * NC + j;
            // fixed-order split-K combine (deterministic)
            l[i] = ((g_logits_part[0][o] + g_logits_part[1][o])
                  + (g_logits_part[2][o] + g_logits_part[3][o]));
            m = fmaxf(m, l[i]);
        } else l[i] = -INFINITY;
    }
    m = warpMax(m);
    if ((t & 31) == 0) red[w] = m;
    __syncthreads();
    float rowmax = red[0];
    #pragma unroll
    for (int i = 1; i < 8; ++i) rowmax = fmaxf(rowmax, red[i]);
    __syncthreads();

    float e[4]; float ssum = 0.f;
    #pragma unroll
    for (int i = 0; i < 4; ++i) {
        int j = t + i * 256;
        e[i] = (j < NC) ? __expf(l[i] - rowmax) : 0.f;
        ssum += e[i];
    }
    ssum = warpSum(ssum);
    if ((t & 31) == 0) red[w] = ssum;
    __syncthreads();
    float tot = 0.f;
    #pragma unroll
    for (int i = 0; i < 8; ++i) tot += red[i];   // same fixed order on all threads
    float inv = 1.0f / tot;
    __syncthreads();

    int tgt = targets[b];
    float s2 = 0.f;
    #pragma unroll
    for (int i = 0; i < 4; ++i) {
        int j = t + i * 256;
        if (j < NC) {
            float p = e[i] * inv;
            pdst[(size_t)b * NC + j] = p;
            if (j == tgt) ptgt = p;
            s2 += __expf(p);          // p in (0,1]: no overflow, no shift
        }
    }
    s2 = warpSum(s2);
    if ((t & 31) == 0) red[w] = s2;
    __syncthreads();
    if (t == 0) {
        float tot2 = 0.f;
        #pragma unroll
        for (int i = 0; i < 8; ++i) tot2 += red[i];
        g_ce[b] = logf(tot2) - ptgt;
    }
}

// ============================================================================
// Kernel 5: loss = -mean(ce). 1 warp, deterministic fixed-order reduce.
// ============================================================================
__global__ void k5_loss(float* __restrict__ out, int loss_idx) {
    int t = threadIdx.x;   // 32 threads
    float s = 0.f;
    #pragma unroll
    for (int i = 0; i < 4; ++i) s += g_ce[t * 4 + i];
    #pragma unroll
    for (int off = 16; off > 0; off >>= 1)
        s += __shfl_down_sync(0xffffffffu, s, off);
    if (t == 0 && loss_idx >= 0)
        out[loss_idx] = -(s * (1.0f / BB));
}

// ============================================================================
extern "C" void kernel_launch(void* const* d_in, const int* in_sizes, int n_in,
                              void* d_out, int out_size) {
    const float* inputs     = (const float*)d_in[0];   // [128,3,224,224]
    const float* patch_grad = (const float*)d_in[1];   // [128,196,768]
    const float* attack_w   = (const float*)d_in[2];   // [3,224,224]
    const float* w_cls      = (const float*)d_in[3];   // [588,1000]
    const int*   targets    = (const int*)d_in[4];     // [128]
    float* out = (float*)d_out;

    (void)in_sizes; (void)n_in;

    // Where do the probs / loss go?
    float* pdst = out;
    if (out_size < BB * NC) {
        float* g_logits_dev = nullptr;
        cudaGetSymbolAddress((void**)&g_logits_dev, g_logits);
        pdst = g_logits_dev;
    }
    int loss_idx = -1;
    if (out_size >= BB * NC + 1)      loss_idx = BB * NC;
    else if (out_size == 1)           loss_idx = 0;

    k1_pool_and_reduce<<<POOL_BLOCKS + GRAD_BLOCKS, 224>>>(inputs, attack_w, patch_grad);
    k2_topk_mask<<<1, 640>>>();
    {
        dim3 grid(NC / BN + ((NC % BN) ? 1 : 0), BB / BM, SPLITK);   // (16, 8, 4)
        k3_gemm<<<grid, 128>>>(w_cls);
    }
    k4_softmax_ce<<<BB, 256>>>(targets, pdst);
    k5_loss<<<1, 32>>>(out, loss_idx);
}

// round 12
// speedup vs baseline: 2.6087x; 1.1124x over previous
#include <cuda_runtime.h>
#include <math.h>

// Problem constants
#define BB      128
#define CC      3
#define HH      224
#define PN      14          // patches per side
#define PS      16          // patch size
#define NP      196         // PN*PN
#define DD      768
#define NC      1000
#define TOPK    20
#define KDIM    588         // C*NP
#define NPART   16          // partials for patch_grad reduction (8 batches each)
#define SPLITK  4
#define KSEG    147         // KDIM / SPLITK

// -------- scratch (device globals; no runtime allocation) --------
__device__ float g_patch_partial[NP * NPART];
__device__ float g_attack_pooled[KDIM];          // c*196 + px*14 + py
__device__ float g_pooled_in[BB * KDIM];         // [b][c*196 + p]
__device__ float g_logits_part[SPLITK][BB * NC]; // split-K partials
__device__ float g_v[NC];                        // batch-independent mask term
__device__ float g_probs_fallback[BB * NC];
__device__ float g_ce[BB];
__device__ int   g_ctr;                          // last-block counter (reset by k1)

// ============================================================================
// Kernel 1 (fused, HBM-bound): pool inputs+attack_w 16x16 means AND reduce
// patch_grad over (batch, dim). Two independent 77MB streams in one grid.
//   Pool blocks: 129*3*14 = 5418  (bb==128 -> attack_w)
//   Grad blocks: 196*16   = 3136  (float4, fully unrolled: 128B/thread MLP)
// blockDim = 224. Also resets g_ctr (deterministic per-call init).
// ============================================================================
#define POOL_BLOCKS (129 * CC * PN)   // 5418
#define GRAD_BLOCKS (NP * NPART)      // 3136

__global__ void k1_pool_and_reduce(const float* __restrict__ inputs,
                                   const float* __restrict__ attack_w,
                                   const float* __restrict__ patch_grad) {
    int blk = blockIdx.x;
    int t   = threadIdx.x;   // 0..223

    if (blk == 0 && t == 0) g_ctr = 0;

    if (blk < POOL_BLOCKS) {
        int bb  = blk / (CC * PN);
        int rem = blk % (CC * PN);
        int c   = rem / PN;
        int px  = rem % PN;
        const float* src = (bb < BB)
            ? inputs   + ((size_t)(bb * CC + c) * HH + px * PS) * HH
            : attack_w + ((size_t)c * HH + px * PS) * HH;
        // thread t sums column t over the 16 rows of this patch-row (MLP=16)
        float acc = 0.f;
        #pragma unroll
        for (int r = 0; r < PS; ++r) acc += src[r * HH + t];
        // reduce within groups of 16 lanes (one group per output patch column)
        #pragma unroll
        for (int off = 8; off > 0; off >>= 1)
            acc += __shfl_down_sync(0xffffffffu, acc, off, 16);
        if ((t & 15) == 0) {
            int iy  = t >> 4;                       // 0..13
            float v = acc * (1.0f / 256.0f);        // 16x16 mean
            int idx = c * NP + px * PN + iy;
            if (bb < BB) g_pooled_in[bb * KDIM + idx] = v;
            else         g_attack_pooled[idx]          = v;
        }
    } else {
        int gid  = blk - POOL_BLOCKS;
        int p    = gid >> 4;            // patch index
        int part = gid & 15;
        int b0   = part * (BB / NPART); // 8 batches per part
        float acc = 0.f;
        if (t < DD / 4) {               // 192 threads carry float4 lanes
            #pragma unroll
            for (int bi = 0; bi < BB / NPART; ++bi) {
                const float4 v = reinterpret_cast<const float4*>(
                    patch_grad + ((size_t)(b0 + bi) * NP + p) * DD)[t];
                acc += (v.x + v.y) + (v.z + v.w);
            }
        }
        // deterministic block reduce: warp shfl tree, then 7 partials serially
        #pragma unroll
        for (int off = 16; off > 0; off >>= 1)
            acc += __shfl_down_sync(0xffffffffu, acc, off);
        __shared__ float ws[7];
        if ((t & 31) == 0) ws[t >> 5] = acc;
        __syncthreads();
        if (t == 0) {
            float s = 0.f;
            #pragma unroll
            for (int w = 0; w < 7; ++w) s += ws[w];
            g_patch_partial[p * NPART + part] = s;
        }
    }
}

// ============================================================================
// Kernel 3 (combined grid):
//  blockIdx.x < 16 : split-K SGEMM partials
//      logits_part[z][128,1000] = pooled_in[128,588] @ w_cls[588,1000] slice
//      (NO mask dependency -- mask folded into the tiny v-term below)
//  blockIdx.x == 16, z == 0 (8 blocks): top-k mask + masked GEMV
//      v[n] = sum over 20 top patches p, channels c of
//             attack_pooled[c*196+p] * w_cls[(c*196+p)*1000 + n]
//      Rank-based top-20 (ties: lower index wins, == jax.lax.top_k order);
//      NOTE: blockDim=128 < NP=196 -> all NP-sized passes use stride loops.
// grid (17, 8, 4), 128 threads.
// ============================================================================
#define BM 16
#define BN 64
#define KT 49

__global__ void k3_gemm_and_v(const float* __restrict__ w_cls) {
    __shared__ float sA[KT][BM];
    __shared__ float sW[KT][BN];
    int t = threadIdx.x;

    if (blockIdx.x < 16) {
        int n0 = blockIdx.x * BN;
        int m0 = blockIdx.y * BM;
        int kb = blockIdx.z * KSEG;
        int tn = t & 15;          // n-group (4 cols)
        int tm = t >> 4;          // m-group (2 rows)
        float acc[2][4] = {{0.f, 0.f, 0.f, 0.f}, {0.f, 0.f, 0.f, 0.f}};

        #pragma unroll
        for (int kt = 0; kt < KSEG / KT; ++kt) {
            int k0 = kb + kt * KT;
            #pragma unroll
            for (int i = t; i < BM * KT; i += 128) {
                int m = i / KT;
                int k = i - m * KT;
                sA[k][m] = g_pooled_in[(m0 + m) * KDIM + k0 + k];
            }
            #pragma unroll
            for (int i = t; i < KT * BN; i += 128) {
                int kk = i >> 6;
                int n  = i & 63;
                int gn = n0 + n;
                sW[kk][n] = (gn < NC) ? w_cls[(size_t)(k0 + kk) * NC + gn] : 0.0f;
            }
            __syncthreads();
            #pragma unroll 7
            for (int k = 0; k < KT; ++k) {
                float2 a = *(const float2*)&sA[k][tm * 2];
                float4 w = *(const float4*)&sW[k][tn * 4];
                acc[0][0] += a.x * w.x; acc[0][1] += a.x * w.y;
                acc[0][2] += a.x * w.z; acc[0][3] += a.x * w.w;
                acc[1][0] += a.y * w.x; acc[1][1] += a.y * w.y;
                acc[1][2] += a.y * w.z; acc[1][3] += a.y * w.w;
            }
            __syncthreads();
        }
        float* dst = g_logits_part[blockIdx.z];
        #pragma unroll
        for (int r = 0; r < 2; ++r) {
            int m = m0 + tm * 2 + r;
            #pragma unroll
            for (int j = 0; j < 4; ++j) {
                int n = n0 + tn * 4 + j;
                if (n < NC) dst[m * NC + n] = acc[r][j];
            }
        }
    } else {
        if (blockIdx.z != 0) return;          // only 8 v-blocks (y = 0..7)
        __shared__ float         sv[NP];
        __shared__ unsigned char smask[NP];
        __shared__ int           plist[TOPK];
        // sum_patch from fixed-order partial combine (stride loop: NP > 128)
        for (int i = t; i < NP; i += 128) {
            float v = 0.f;
            #pragma unroll
            for (int q = 0; q < NPART; ++q) v += g_patch_partial[i * NPART + q];
            sv[i] = v;
        }
        __syncthreads();
        // rank-based top-20; ties broken by lower index (jax.lax.top_k order)
        for (int i = t; i < NP; i += 128) {
            float v = sv[i];
            int rank = 0;
            for (int j = 0; j < NP; ++j) {
                float u = sv[j];
                rank += (u > v) || (u == v && j < i);
            }
            smask[i] = (rank < TOPK) ? 1 : 0;
        }
        __syncthreads();
        if (t == 0) {                          // deterministic ascending list
            int cnt = 0;
            for (int p = 0; p < NP; ++p)
                if (smask[p] && cnt < TOPK) plist[cnt++] = p;
        }
        __syncthreads();

        int n = blockIdx.y * 125 + t;          // 8 blocks x 125 cols = 1000
        if (t < 125) {
            float acc = 0.f;
            #pragma unroll 2
            for (int i = 0; i < TOPK; ++i) {
                int p = plist[i];
                #pragma unroll
                for (int c = 0; c < CC; ++c) {
                    int k = c * NP + p;
                    acc += g_attack_pooled[k] * w_cls[(size_t)k * NC + n];
                }
            }
            g_v[n] = acc;
        }
    }
}

// ============================================================================
// Kernel 4: combine split-K partials + v (fixed order), per-row softmax ->
// probs (written to pdst), then log_softmax of the PROBS (reference quirk):
//   ce[b] = log(sum_j exp(p_j)) - p_target
// exp(p) for p in (0,1] evaluated with a degree-4 Taylor on the FMA pipe
// (abs err <= 1e-2 on a sum of ~1000 -> ~1e-5 in ce; tolerance 1e-3).
// Fused final loss via deterministic last-block reduction.
// grid = 128 blocks, 256 threads.
// ============================================================================
__device__ __forceinline__ float warpMax(float v) {
    #pragma unroll
    for (int o = 16; o > 0; o >>= 1) v = fmaxf(v, __shfl_xor_sync(0xffffffffu, v, o));
    return v;
}
__device__ __forceinline__ float warpSum(float v) {
    #pragma unroll
    for (int o = 16; o > 0; o >>= 1) v += __shfl_xor_sync(0xffffffffu, v, o);
    return v;
}

__global__ void k4_softmax_ce(const int* __restrict__ targets,
                              float* __restrict__ pdst,
                              float* __restrict__ out, int loss_idx) {
    int b = blockIdx.x;
    int t = threadIdx.x;
    int w = t >> 5;
    __shared__ float red[8];
    __shared__ float ptgt;
    __shared__ int   slast;

    float l[4];
    float m = -INFINITY;
    #pragma unroll
    for (int i = 0; i < 4; ++i) {
        int j = t + i * 256;
        if (j < NC) {
            size_t o = (size_t)b * NC + j;
            l[i] = ((g_logits_part[0][o] + g_logits_part[1][o])
                  + (g_logits_part[2][o] + g_logits_part[3][o])) + g_v[j];
            m = fmaxf(m, l[i]);
        } else l[i] = -INFINITY;
    }
    m = warpMax(m);
    if ((t & 31) == 0) red[w] = m;
    __syncthreads();
    float rowmax = red[0];
    #pragma unroll
    for (int i = 1; i < 8; ++i) rowmax = fmaxf(rowmax, red[i]);
    __syncthreads();

    float e[4]; float ssum = 0.f;
    #pragma unroll
    for (int i = 0; i < 4; ++i) {
        int j = t + i * 256;
        e[i] = (j < NC) ? __expf(l[i] - rowmax) : 0.f;
        ssum += e[i];
    }
    ssum = warpSum(ssum);
    if ((t & 31) == 0) red[w] = ssum;
    __syncthreads();
    float tot = 0.f;
    #pragma unroll
    for (int i = 0; i < 8; ++i) tot += red[i];   // same fixed order on all threads
    float inv = 1.0f / tot;
    __syncthreads();

    int tgt = targets[b];
    float s2 = 0.f;
    #pragma unroll
    for (int i = 0; i < 4; ++i) {
        int j = t + i * 256;
        if (j < NC) {
            float p = e[i] * inv;
            pdst[(size_t)b * NC + j] = p;
            if (j == tgt) ptgt = p;
            // exp(p), p in (0,1]: 1 + p(1 + p(1/2 + p(1/6 + p/24)))
            float q = fmaf(p, 1.0f / 24.0f, 1.0f / 6.0f);
            q = fmaf(p, q, 0.5f);
            q = fmaf(p, q, 1.0f);
            q = fmaf(p, q, 1.0f);
            s2 += q;
        }
    }
    s2 = warpSum(s2);
    if ((t & 31) == 0) red[w] = s2;
    __syncthreads();
    if (t == 0) {
        float tot2 = 0.f;
        #pragma unroll
        for (int i = 0; i < 8; ++i) tot2 += red[i];
        g_ce[b] = logf(tot2) - ptgt;
        __threadfence();
        int done = atomicAdd(&g_ctr, 1);
        slast = (done == BB - 1) ? 1 : 0;
    }
    __syncthreads();
    // last block: deterministic fixed-order loss = -mean(ce)
    if (slast && t < 32 && loss_idx >= 0) {
        __threadfence();
        float s = 0.f;
        #pragma unroll
        for (int i = 0; i < 4; ++i) s += g_ce[t * 4 + i];
        #pragma unroll
        for (int off = 16; off > 0; off >>= 1)
            s += __shfl_down_sync(0xffffffffu, s, off);
        if (t == 0) out[loss_idx] = -(s * (1.0f / BB));
    }
}

// ============================================================================
extern "C" void kernel_launch(void* const* d_in, const int* in_sizes, int n_in,
                              void* d_out, int out_size) {
    const float* inputs     = (const float*)d_in[0];   // [128,3,224,224]
    const float* patch_grad = (const float*)d_in[1];   // [128,196,768]
    const float* attack_w   = (const float*)d_in[2];   // [3,224,224]
    const float* w_cls      = (const float*)d_in[3];   // [588,1000]
    const int*   targets    = (const int*)d_in[4];     // [128]
    float* out = (float*)d_out;

    (void)in_sizes; (void)n_in;

    // Where do the probs / loss go?
    float* pdst = out;
    if (out_size < BB * NC) {
        float* fb = nullptr;
        cudaGetSymbolAddress((void**)&fb, g_probs_fallback);
        pdst = fb;
    }
    int loss_idx = -1;
    if (out_size >= BB * NC + 1)      loss_idx = BB * NC;
    else if (out_size == 1)           loss_idx = 0;

    k1_pool_and_reduce<<<POOL_BLOCKS + GRAD_BLOCKS, 224>>>(inputs, attack_w, patch_grad);
    {
        dim3 grid(17, 8, SPLITK);   // 16 n-tiles GEMM + 1 column of v-blocks
        k3_gemm_and_v<<<grid, 128>>>(w_cls);
    }
    k4_softmax_ce<<<BB, 256>>>(targets, pdst, out, loss_idx);
}